// round 5
// baseline (speedup 1.0000x reference)
#include <cuda_runtime.h>
#include <cuda_bf16.h>

#define B_IMG 48
#define H_DIM 512
#define W_DIM 512
#define K_K   33
#define N_PIX (H_DIM * W_DIM)
#define N_ZERO (N_PIX - 961)            // nonzero hann entries = (K-2)^2

#define THR      256
#define BLKX     12                     // blocks per image (block 0 = patch block)
#define NSTREAM  (BLKX - 1)             // 11 streaming blocks per image
#define F4_PER_IMG (N_PIX / 4)          // 65536
#define CHUNK ((F4_PER_IMG + NSTREAM - 1) / NSTREAM)

// Persistent scratch; reset to 0 before kernel exit => replay-deterministic.
__device__ float g_sum[B_IMG];     // per-image sum of softplus(pred)
__device__ float g_pp [B_IMG];     // patch: sum pred over 33x33
__device__ float g_pzw[B_IMG];     // patch: sum hann*bce (nonzero hann)
__device__ float g_pz [B_IMG];     // patch: sum bce (nonzero hann)
__device__ float g_ph [B_IMG];     // hann sum
__device__ int   g_cnt[B_IMG];     // per-image arrival counter
__device__ float g_loss;           // accumulated loss
__device__ int   g_done;           // finished-image counter

#define LN2 0.6931471805599453f

__device__ __forceinline__ float softplus_f(float x) {
    float z = __expf(-fabsf(x));
    return fmaxf(x, 0.0f) + __logf(1.0f + z);
}

__device__ __forceinline__ float z_of(float x) {
    return __expf(-fabsf(x));           // MUFU.EX2 (+1 FMUL fold)
}

// Grouped log-term for 8 elements: returns log2(prod(1+z_i)); accumulates
// sum(x) and sum(|x|) for the relu half.
__device__ __forceinline__ float g8(float4 A, float4 B, float& sx, float& sa) {
    sx += ((A.x + A.y) + (A.z + A.w)) + ((B.x + B.y) + (B.z + B.w));
    sa += ((fabsf(A.x) + fabsf(A.y)) + (fabsf(A.z) + fabsf(A.w)))
        + ((fabsf(B.x) + fabsf(B.y)) + (fabsf(B.z) + fabsf(B.w)));
    float z0 = z_of(A.x), z1 = z_of(A.y), z2 = z_of(A.z), z3 = z_of(A.w);
    float z4 = z_of(B.x), z5 = z_of(B.y), z6 = z_of(B.z), z7 = z_of(B.w);
    // w = prod(1+z) - 1, built as w_ab = wa + wb + wa*wb
    float w01 = fmaf(z0, z1, z0 + z1), w23 = fmaf(z2, z3, z2 + z3);
    float w45 = fmaf(z4, z5, z4 + z5), w67 = fmaf(z6, z7, z6 + z7);
    float wA  = fmaf(w01, w23, w01 + w23);
    float wB  = fmaf(w45, w67, w45 + w67);
    float w   = fmaf(wA, wB, wA + wB);
    return __log2f(1.0f + w);
}

// 4-element variant for the remainder loop.
__device__ __forceinline__ float g4(float4 A, float& sx, float& sa) {
    sx += (A.x + A.y) + (A.z + A.w);
    sa += (fabsf(A.x) + fabsf(A.y)) + (fabsf(A.z) + fabsf(A.w));
    float z0 = z_of(A.x), z1 = z_of(A.y), z2 = z_of(A.z), z3 = z_of(A.w);
    float w01 = fmaf(z0, z1, z0 + z1), w23 = fmaf(z2, z3, z2 + z3);
    float w   = fmaf(w01, w23, w01 + w23);
    return __log2f(1.0f + w);
}

__device__ __forceinline__ float blockReduceSum(float v) {
    __shared__ float sh[32];
    __syncthreads();
    int lane = threadIdx.x & 31;
    int wid  = threadIdx.x >> 5;
    #pragma unroll
    for (int o = 16; o > 0; o >>= 1) v += __shfl_down_sync(0xffffffffu, v, o);
    if (lane == 0) sh[wid] = v;
    __syncthreads();
    int nw = (blockDim.x + 31) >> 5;
    v = (threadIdx.x < nw) ? sh[lane] : 0.0f;
    if (wid == 0) {
        #pragma unroll
        for (int o = 16; o > 0; o >>= 1) v += __shfl_down_sync(0xffffffffu, v, o);
    }
    return v;   // valid in thread 0
}

__global__ void __launch_bounds__(THR, 4)
fused_hann_loss(const float* __restrict__ pred,
                const float* __restrict__ tgt,
                const float* __restrict__ hann,
                float* __restrict__ out) {
    const int b  = blockIdx.y;
    const int bx = blockIdx.x;
    const int t  = threadIdx.x;
    const float* P = pred + (size_t)b * N_PIX;

    if (bx != 0) {
        // ------------- streaming blocks: grouped softplus sum ---------------
        const float4* P4 = reinterpret_cast<const float4*>(P);
        const int beg = (bx - 1) * CHUNK;
        const int end = min(beg + CHUNK, F4_PER_IMG);

        float sx = 0.0f, sa = 0.0f, slg = 0.0f;
        int j = beg + t;
        const int lim = end - 3 * THR;
        for (; j < lim; j += 4 * THR) {            // front-batched 4x LDG.128
            float4 a = P4[j];
            float4 c = P4[j +     THR];
            float4 d = P4[j + 2 * THR];
            float4 e = P4[j + 3 * THR];
            slg += g8(a, c, sx, sa);
            slg += g8(d, e, sx, sa);
        }
        for (; j < end; j += THR) {
            slg += g4(P4[j], sx, sa);
        }
        // softplus sum = relu-part + ln2 * log2-part
        float v = fmaf(LN2, slg, 0.5f * (sx + sa));
        v = blockReduceSum(v);
        if (t == 0) {
            atomicAdd(&g_sum[b], v);
            __threadfence();                       // release partial sum
        }
    } else {
        // ------------- patch block: locate + 33x33 patch sums ---------------
        const float* T = tgt + (size_t)b * N_PIX;
        __shared__ int s_min, s_ys, s_xs;
        if (t == 0) s_min = 0x7fffffff;
        __syncthreads();

        // 16x16 sample grid at stride 32 always hits the 33x33 ones block.
        {
            int sy = (t >> 4) << 5;
            int sx_ = (t & 15) << 5;
            if (T[sy * W_DIM + sx_] == 1.0f) atomicMin(&s_min, sy * W_DIM + sx_);
        }
        __syncthreads();

        int y0 = s_min / W_DIM;
        int x0 = s_min - y0 * W_DIM;

        if (t < 32) {
            int x = x0 - 32 + t;
            bool one = (x >= 0) && (T[y0 * W_DIM + x] == 1.0f);
            unsigned m = __ballot_sync(0xffffffffu, one);
            if (t == 0) s_xs = m ? (x0 - 32 + (__ffs(m) - 1)) : x0;
        } else if (t < 64) {
            int l = t - 32;
            int y = y0 - 32 + l;
            bool one = (y >= 0) && (T[y * W_DIM + x0] == 1.0f);
            unsigned m = __ballot_sync(0xffffffffu, one);
            if (l == 0) s_ys = m ? (y0 - 32 + (__ffs(m) - 1)) : y0;
        }
        __syncthreads();
        const int ys = s_ys;
        const int xs = s_xs;

        float sum_p = 0.0f, sum_zw = 0.0f, sum_z = 0.0f, sum_h = 0.0f;
        for (int idx = t; idx < K_K * K_K; idx += THR) {
            int r = idx / K_K;
            int c = idx - r * K_K;
            float p  = P[(ys + r) * W_DIM + (xs + c)];
            float hv = hann[idx];
            sum_p += p;
            sum_h += hv;
            if (hv != 0.0f) {
                float bce = softplus_f(p) - p;    // target==1 on patch
                sum_zw += hv * bce;
                sum_z  += bce;
            }
        }
        float r_p  = blockReduceSum(sum_p);
        float r_zw = blockReduceSum(sum_zw);
        float r_z  = blockReduceSum(sum_z);
        float r_h  = blockReduceSum(sum_h);

        if (t == 0) {
            g_pp [b] = r_p;
            g_pzw[b] = r_zw;
            g_pz [b] = r_z;
            g_ph [b] = r_h;
            __threadfence();                      // release patch results
        }
    }

    // ------------- arrival + per-image combine (tiny) ------------------------
    if (t == 0) {
        int old = atomicAdd(&g_cnt[b], 1);
        if (old == BLKX - 1) {                    // last arrival for image b
            __threadfence();                      // acquire all published data
            atomicExch(&g_cnt[b], 0);
            float total_sp = atomicExch(&g_sum[b], 0.0f);
            float r_p  = atomicExch(&g_pp [b], 0.0f);
            float r_zw = atomicExch(&g_pzw[b], 0.0f);
            float r_z  = atomicExch(&g_pz [b], 0.0f);
            float r_h  = atomicExch(&g_ph [b], 0.0f);

            float bce_total = total_sp - r_p;
            float loss = r_zw / (2.0f * r_h)
                       + (bce_total - r_z) * (1.0f / (2.0f * (float)N_ZERO));

            atomicAdd(&g_loss, loss);
            __threadfence();
            int od = atomicAdd(&g_done, 1);
            if (od == B_IMG - 1) {
                __threadfence();
                float tot = atomicExch(&g_loss, 0.0f);
                atomicExch(&g_done, 0);
                out[0] = tot * (1.0f / (float)B_IMG);
            }
        }
    }
}

extern "C" void kernel_launch(void* const* d_in, const int* in_sizes, int n_in,
                              void* d_out, int out_size) {
    const float* pred = (const float*)d_in[0];
    const float* tgt  = (const float*)d_in[1];
    const float* hann = (const float*)d_in[2];
    float* out = (float*)d_out;

    dim3 grid(BLKX, B_IMG);
    fused_hann_loss<<<grid, THR>>>(pred, tgt, hann, out);
}

// round 6
// speedup vs baseline: 1.1604x; 1.1604x over previous
#include <cuda_runtime.h>
#include <cuda_bf16.h>

#define B_IMG 48
#define H_DIM 512
#define W_DIM 512
#define K_K   33
#define N_PIX (H_DIM * W_DIM)
#define N_ZERO (N_PIX - 961)            // nonzero hann entries = (K-2)^2

#define THR      256
#define NSTREAM  840                    // streaming blocks (flat chunks)
#define TOTB     (B_IMG + NSTREAM)      // 888 = 148 SMs * 6 blocks
#define N4       (B_IMG * N_PIX / 4)    // 3,145,728 float4 total (flat)
#define CHUNK    ((N4 + NSTREAM - 1) / NSTREAM)   // 3745

// Persistent scratch; reset to 0 before kernel exit => replay-deterministic.
__device__ float g_total;          // global sum of softplus(pred), all images
__device__ float g_partial;        // sum of per-image patch corrections
__device__ int   g_done;           // finished-block counter

#define LN2 0.6931471805599453f

__device__ __forceinline__ float softplus_f(float x) {
    float z = __expf(-fabsf(x));
    return fmaxf(x, 0.0f) + __logf(1.0f + z);
}

__device__ __forceinline__ float z_of(float x) {
    return __expf(-fabsf(x));           // MUFU.EX2 (+FMUL fold)
}

// Grouped log-term for 8 elements: returns log2(prod(1+z_i)); accumulates
// sum(x) and sum(|x|) for the relu half of softplus.
__device__ __forceinline__ float g8(float4 A, float4 B, float& sx, float& sa) {
    sx += ((A.x + A.y) + (A.z + A.w)) + ((B.x + B.y) + (B.z + B.w));
    sa += ((fabsf(A.x) + fabsf(A.y)) + (fabsf(A.z) + fabsf(A.w)))
        + ((fabsf(B.x) + fabsf(B.y)) + (fabsf(B.z) + fabsf(B.w)));
    float z0 = z_of(A.x), z1 = z_of(A.y), z2 = z_of(A.z), z3 = z_of(A.w);
    float z4 = z_of(B.x), z5 = z_of(B.y), z6 = z_of(B.z), z7 = z_of(B.w);
    float w01 = fmaf(z0, z1, z0 + z1), w23 = fmaf(z2, z3, z2 + z3);
    float w45 = fmaf(z4, z5, z4 + z5), w67 = fmaf(z6, z7, z6 + z7);
    float wA  = fmaf(w01, w23, w01 + w23);
    float wB  = fmaf(w45, w67, w45 + w67);
    float w   = fmaf(wA, wB, wA + wB);
    return __log2f(1.0f + w);
}

__device__ __forceinline__ float g4(float4 A, float& sx, float& sa) {
    sx += (A.x + A.y) + (A.z + A.w);
    sa += (fabsf(A.x) + fabsf(A.y)) + (fabsf(A.z) + fabsf(A.w));
    float z0 = z_of(A.x), z1 = z_of(A.y), z2 = z_of(A.z), z3 = z_of(A.w);
    float w01 = fmaf(z0, z1, z0 + z1), w23 = fmaf(z2, z3, z2 + z3);
    float w   = fmaf(w01, w23, w01 + w23);
    return __log2f(1.0f + w);
}

__device__ __forceinline__ float blockReduceSum(float v) {
    __shared__ float sh[32];
    __syncthreads();
    int lane = threadIdx.x & 31;
    int wid  = threadIdx.x >> 5;
    #pragma unroll
    for (int o = 16; o > 0; o >>= 1) v += __shfl_down_sync(0xffffffffu, v, o);
    if (lane == 0) sh[wid] = v;
    __syncthreads();
    int nw = (blockDim.x + 31) >> 5;
    v = (threadIdx.x < nw) ? sh[lane] : 0.0f;
    if (wid == 0) {
        #pragma unroll
        for (int o = 16; o > 0; o >>= 1) v += __shfl_down_sync(0xffffffffu, v, o);
    }
    return v;   // valid in thread 0
}

__global__ void __launch_bounds__(THR, 6)
fused_hann_loss(const float* __restrict__ pred,
                const float* __restrict__ tgt,
                const float* __restrict__ hann,
                float* __restrict__ out) {
    const int blk = blockIdx.x;
    const int t   = threadIdx.x;

    if (blk >= B_IMG) {
        // ------------- streaming block: flat grouped softplus sum -----------
        const float4* P4 = reinterpret_cast<const float4*>(pred);
        const int s   = blk - B_IMG;
        const int beg = s * CHUNK;
        const int end = min(beg + CHUNK, N4);

        float sx = 0.0f, sa = 0.0f, slg = 0.0f;
        int j = beg + t;
        const int lim = end - THR;            // pair (j, j+THR) both valid
        for (; j < lim; j += 2 * THR) {
            float4 a = P4[j];
            float4 c = P4[j + THR];
            slg += g8(a, c, sx, sa);
        }
        if (j < end) slg += g4(P4[j], sx, sa);

        float v = fmaf(LN2, slg, 0.5f * (sx + sa));
        v = blockReduceSum(v);
        if (t == 0) {
            atomicAdd(&g_total, v);
            __threadfence();                  // release partial sum
        }
    } else {
        // ------------- patch block: locate + 33x33 patch sums ---------------
        const int b = blk;
        const float* P = pred + (size_t)b * N_PIX;
        const float* T = tgt  + (size_t)b * N_PIX;
        __shared__ int s_min, s_ys, s_xs;
        if (t == 0) s_min = 0x7fffffff;
        __syncthreads();

        // 16x16 sample grid at stride 32 always hits the 33x33 ones block.
        {
            int sy = (t >> 4) << 5;
            int sx_ = (t & 15) << 5;
            if (T[sy * W_DIM + sx_] == 1.0f) atomicMin(&s_min, sy * W_DIM + sx_);
        }
        __syncthreads();

        int y0 = s_min / W_DIM;
        int x0 = s_min - y0 * W_DIM;

        if (t < 32) {
            int x = x0 - 32 + t;
            bool one = (x >= 0) && (T[y0 * W_DIM + x] == 1.0f);
            unsigned m = __ballot_sync(0xffffffffu, one);
            if (t == 0) s_xs = m ? (x0 - 32 + (__ffs(m) - 1)) : x0;
        } else if (t < 64) {
            int l = t - 32;
            int y = y0 - 32 + l;
            bool one = (y >= 0) && (T[y * W_DIM + x0] == 1.0f);
            unsigned m = __ballot_sync(0xffffffffu, one);
            if (l == 0) s_ys = m ? (y0 - 32 + (__ffs(m) - 1)) : y0;
        }
        __syncthreads();
        const int ys = s_ys;
        const int xs = s_xs;

        float sum_p = 0.0f, sum_zw = 0.0f, sum_z = 0.0f, sum_h = 0.0f;
        for (int idx = t; idx < K_K * K_K; idx += THR) {
            int r = idx / K_K;
            int c = idx - r * K_K;
            float p  = P[(ys + r) * W_DIM + (xs + c)];
            float hv = hann[idx];
            sum_p += p;
            sum_h += hv;
            if (hv != 0.0f) {
                float bce = softplus_f(p) - p;   // target==1 on patch
                sum_zw += hv * bce;
                sum_z  += bce;
            }
        }
        float r_p  = blockReduceSum(sum_p);
        float r_zw = blockReduceSum(sum_zw);
        float r_z  = blockReduceSum(sum_z);
        float r_h  = blockReduceSum(sum_h);

        if (t == 0) {
            // per-image correction: full loss_i minus the global-sum term
            float part = r_zw / (2.0f * r_h)
                       - (r_p + r_z) * (1.0f / (2.0f * (float)N_ZERO));
            atomicAdd(&g_partial, part);
            __threadfence();                  // release partial
        }
    }

    // ------------- arrival + final combine (tiny) ----------------------------
    if (t == 0) {
        int old = atomicAdd(&g_done, 1);
        if (old == TOTB - 1) {                // last arrival chip-wide
            __threadfence();                  // acquire all published data
            atomicExch(&g_done, 0);
            float tot  = atomicExch(&g_total,   0.0f);
            float part = atomicExch(&g_partial, 0.0f);
            float loss = part + tot * (1.0f / (2.0f * (float)N_ZERO));
            out[0] = loss * (1.0f / (float)B_IMG);
        }
    }
}

extern "C" void kernel_launch(void* const* d_in, const int* in_sizes, int n_in,
                              void* d_out, int out_size) {
    const float* pred = (const float*)d_in[0];
    const float* tgt  = (const float*)d_in[1];
    const float* hann = (const float*)d_in[2];
    float* out = (float*)d_out;

    fused_hann_loss<<<TOTB, THR>>>(pred, tgt, hann, out);
}